// round 3
// baseline (speedup 1.0000x reference)
#include <cuda_runtime.h>

// Problem dims (fixed by the dataset)
#define Bn 8
#define Cn 19
#define Hn 384
#define Wn 384
#define NPIX (Bn * Hn * Wn)
#define HWn (Hn * Wn)
#define BOUND 777  // B + C + H + W = 8+1+384+384

// Scratch (allocation-free rule: __device__ globals)
__device__ unsigned char  g_pred[NPIX];
__device__ unsigned short g_vert[NPIX];
__device__ float          g_ce;
__device__ unsigned int   g_border;

// ---------------------------------------------------------------------------
// Kernel 0: zero the accumulators (graph replays must be idempotent).
// ---------------------------------------------------------------------------
__global__ void init_kernel() {
    g_ce = 0.0f;
    g_border = 0u;
}

// ---------------------------------------------------------------------------
// Kernel 1: fused cross-entropy (sum, ignore_index=255) + argmax (pred map).
// 4 pixels per thread via float4 loads; 19 channel float4s in registers.
// exp via MUFU (__expf): only ~19 exps/pixel -> MUFU pipe is not the limiter.
// ---------------------------------------------------------------------------
__global__ void __launch_bounds__(256) ce_argmax_kernel(
    const float* __restrict__ x, const int* __restrict__ tgt) {
    int idx4 = blockIdx.x * blockDim.x + threadIdx.x;  // 0 .. NPIX/4-1
    const int HW4 = HWn / 4;
    int b = idx4 / HW4;
    int hw4 = idx4 - b * HW4;
    const float4* p = (const float4*)(x + (size_t)b * Cn * HWn) + hw4;

    float v[Cn][4];
    #pragma unroll
    for (int c = 0; c < Cn; c++) {
        float4 q = __ldg(p + (size_t)c * HW4);
        v[c][0] = q.x; v[c][1] = q.y; v[c][2] = q.z; v[c][3] = q.w;
    }

    int t[4];
    {
        int4 tq = ((const int4*)tgt)[idx4];
        t[0] = tq.x; t[1] = tq.y; t[2] = tq.z; t[3] = tq.w;
    }

    float nll = 0.0f;
    unsigned int packed_pred = 0;
    #pragma unroll
    for (int k = 0; k < 4; k++) {
        float m = v[0][k];
        int arg = 0;
        float tv = v[0][k];
        #pragma unroll
        for (int c = 1; c < Cn; c++) {
            float vc = v[c][k];
            if (vc > m) { m = vc; arg = c; }     // first-max tie break
            tv = (c == t[k]) ? vc : tv;           // register-resident gather
        }
        packed_pred |= ((unsigned int)arg) << (8 * k);

        float s = 0.0f;
        #pragma unroll
        for (int c = 0; c < Cn; c++) s += __expf(v[c][k] - m);

        if (t[k] != 255) nll += (m + __logf(s)) - tv;
    }
    ((unsigned int*)g_pred)[idx4] = packed_pred;

    // block reduction -> atomicAdd
    #pragma unroll
    for (int o = 16; o > 0; o >>= 1)
        nll += __shfl_down_sync(0xFFFFFFFFu, nll, o);
    __shared__ float ws[8];
    int lane = threadIdx.x & 31, wid = threadIdx.x >> 5;
    if (lane == 0) ws[wid] = nll;
    __syncthreads();
    if (wid == 0) {
        float v2 = (lane < (blockDim.x >> 5)) ? ws[lane] : 0.0f;
        #pragma unroll
        for (int o = 4; o > 0; o >>= 1)
            v2 += __shfl_down_sync(0xFFFFFFFFu, v2, o);
        if (lane == 0) atomicAdd(&g_ce, v2);
    }
}

// ---------------------------------------------------------------------------
// Kernel 2: target borders (on the fly) + vertical 1D nearest-border distance.
// One warp per block (96 blocks -> spread across SMs). Right-neighbor target
// value fetched via shfl instead of a second global load.
// border(i,j) = ((t[i+1,j]-t[i,j]) + (t[i,j+1]-t[i,j])) != 0 (zero-padded).
// ---------------------------------------------------------------------------
__global__ void __launch_bounds__(32) vert_dt_kernel(const int* __restrict__ tgt) {
    int lane = threadIdx.x;
    int j = blockIdx.x * 32 + lane;                  // column 0..383
    int b = blockIdx.y;
    const int* tb = tgt + (size_t)b * HWn;
    unsigned short* gv = g_vert + (size_t)b * HWn;

    int cur = tb[j];
    int curR;
    {
        int sh = __shfl_down_sync(0xFFFFFFFFu, cur, 1);
        curR = (lane == 31) ? ((j < Wn - 1) ? tb[j + 1] : cur) : sh;
    }

    int v = BOUND;
    for (int i = 0; i < Hn; i++) {
        int nxt, nxtR;
        if (i < Hn - 1) {
            nxt = tb[(i + 1) * Wn + j];
            int sh = __shfl_down_sync(0xFFFFFFFFu, nxt, 1);
            nxtR = (lane == 31) ? ((j < Wn - 1) ? tb[(i + 1) * Wn + j + 1] : nxt) : sh;
        } else {
            nxt = cur; nxtR = curR;                  // bottom row: diffs pad to 0
        }
        int diff = (nxt - cur) + (curR - cur);
        int vp1 = v + 1; if (vp1 > BOUND) vp1 = BOUND;
        v = (diff != 0) ? 0 : vp1;
        gv[i * Wn + j] = (unsigned short)v;
        cur = nxt; curR = nxtR;
    }
    int u = BOUND;
    for (int i = Hn - 1; i >= 0; i--) {
        int gval = gv[i * Wn + j];
        int up1 = u + 1; if (up1 > BOUND) up1 = BOUND;
        u = min(gval, up1);
        gv[i * Wn + j] = (unsigned short)u;
    }
}

// ---------------------------------------------------------------------------
// Kernel 3: horizontal Chebyshev stage via incremental expanding window.
// d(j) = min t : min_{|y-j|<=t} g(y) <= t. With dense borders the answer is
// almost always 0 -> expected ~1 iteration. Exact & terminating for any input.
// Fused with pred-border masking and integer border-loss reduction.
// ---------------------------------------------------------------------------
__global__ void __launch_bounds__(Wn) horiz_dt_kernel() {
    __shared__ unsigned short G[Wn];
    __shared__ int wsum[12];

    int row = blockIdx.x;           // 0 .. B*H-1
    int i = row % Hn;
    int j = threadIdx.x;
    int base = row * Wn;

    G[j] = g_vert[base + j];
    __syncthreads();

    int wm = G[j];
    int t = 0;
    while (wm > t) {                // terminates: wm <= BOUND, t -> BOUND
        t++;
        int a = j - t;
        int bb = j + t;
        if (a >= 0)  { int x = G[a];  wm = x < wm ? x : wm; }
        if (bb < Wn) { int x = G[bb]; wm = x < wm ? x : wm; }
    }
    int d = t;

    // pred border at (b, i, j)
    int pidx = base + j;            // == b*HWn + i*Wn + j
    int p0 = g_pred[pidx];
    int pd = (i < Hn - 1) ? (int)g_pred[pidx + Wn] : p0;
    int pr = (j < Wn - 1) ? (int)g_pred[pidx + 1]  : p0;
    int contrib = (((pd - p0) + (pr - p0)) != 0) ? d : 0;

    // integer block reduction (exact) -> u32 atomic
    #pragma unroll
    for (int o = 16; o > 0; o >>= 1)
        contrib += __shfl_down_sync(0xFFFFFFFFu, contrib, o);
    int lane = threadIdx.x & 31, wid = threadIdx.x >> 5;
    if (lane == 0) wsum[wid] = contrib;
    __syncthreads();
    if (wid == 0) {
        int v2 = (lane < 12) ? wsum[lane] : 0;
        #pragma unroll
        for (int o = 8; o > 0; o >>= 1)
            v2 += __shfl_down_sync(0xFFFFFFFFu, v2, o);
        if (lane == 0) atomicAdd(&g_border, (unsigned int)v2);
    }
}

// ---------------------------------------------------------------------------
// Kernel 4: combine.
// ---------------------------------------------------------------------------
__global__ void final_kernel(float* out) {
    out[0] = g_ce + 0.2f * (float)g_border;
}

extern "C" void kernel_launch(void* const* d_in, const int* in_sizes, int n_in,
                              void* d_out, int out_size) {
    const float* slices  = (const float*)d_in[0];
    const int*   targets = (const int*)d_in[1];   // JAX int64 -> int32 (x64 disabled)
    float* out = (float*)d_out;

    init_kernel<<<1, 1>>>();
    ce_argmax_kernel<<<(NPIX / 4) / 256, 256>>>(slices, targets);
    vert_dt_kernel<<<dim3(Wn / 32, Bn), 32>>>(targets);
    horiz_dt_kernel<<<Bn * Hn, Wn>>>();
    final_kernel<<<1, 1>>>(out);
}

// round 4
// speedup vs baseline: 4.0183x; 4.0183x over previous
#include <cuda_runtime.h>

// Problem dims (fixed by the dataset)
#define Bn 8
#define Cn 19
#define Hn 384
#define Wn 384
#define NPIX (Bn * Hn * Wn)
#define HWn (Hn * Wn)
#define BOUND 777  // B + C + H + W = 8+1+384+384

// Scratch (allocation-free rule: __device__ globals), 16B-aligned for uint4 IO
__device__ __align__(16) unsigned char g_pred[NPIX];
__device__ __align__(16) unsigned char g_tb[NPIX];    // target-border bitmap (0/1)
__device__ float        g_ce;
__device__ unsigned int g_border;

// ---------------------------------------------------------------------------
// Kernel 0: zero the accumulators (graph replays must be idempotent).
// ---------------------------------------------------------------------------
__global__ void init_kernel() {
    g_ce = 0.0f;
    g_border = 0u;
}

// ---------------------------------------------------------------------------
// Kernel 1: fused CE(sum, ignore=255) + argmax(pred map) + TARGET BORDER map.
// 4 pixels/thread via float4/int4; 19 channel float4s in registers.
// border(i,j) = ((t[i+1,j]-t[i,j]) + (t[i,j+1]-t[i,j])) != 0, zero-padded.
// ---------------------------------------------------------------------------
__global__ void __launch_bounds__(256) ce_kernel(
    const float* __restrict__ x, const int* __restrict__ tgt) {
    int idx4 = blockIdx.x * blockDim.x + threadIdx.x;  // 0 .. NPIX/4-1
    const int HW4 = HWn / 4;
    int b = idx4 / HW4;
    int hw4 = idx4 - b * HW4;
    const float4* p = (const float4*)(x + (size_t)b * Cn * HWn) + hw4;

    float v[Cn][4];
    #pragma unroll
    for (int c = 0; c < Cn; c++) {
        float4 q = __ldg(p + (size_t)c * HW4);
        v[c][0] = q.x; v[c][1] = q.y; v[c][2] = q.z; v[c][3] = q.w;
    }

    int hw = hw4 * 4;
    int i = hw / Wn;                 // row (4 pixels always within one row)
    int j0 = hw - i * Wn;            // col of pixel 0
    int gbase = b * HWn + hw;        // global pixel index of pixel 0

    int4 tq = __ldg((const int4*)tgt + idx4);
    int t[5];
    t[0] = tq.x; t[1] = tq.y; t[2] = tq.z; t[3] = tq.w;
    t[4] = (j0 + 4 < Wn) ? __ldg(tgt + gbase + 4) : t[3];   // row-end pad

    int td[4];
    if (i < Hn - 1) {
        int4 dq = __ldg((const int4*)tgt + idx4 + Wn / 4);
        td[0] = dq.x; td[1] = dq.y; td[2] = dq.z; td[3] = dq.w;
    } else {
        td[0] = t[0]; td[1] = t[1]; td[2] = t[2]; td[3] = t[3];  // bottom pad
    }

    float nll = 0.0f;
    unsigned int packed_pred = 0, packed_border = 0;
    #pragma unroll
    for (int k = 0; k < 4; k++) {
        float m = v[0][k];
        int arg = 0;
        float tv = v[0][k];
        #pragma unroll
        for (int c = 1; c < Cn; c++) {
            float vc = v[c][k];
            if (vc > m) { m = vc; arg = c; }     // first-max tie break
            tv = (c == t[k]) ? vc : tv;           // register-resident gather
        }
        packed_pred |= ((unsigned int)arg) << (8 * k);

        int bd = (((td[k] - t[k]) + (t[k + 1] - t[k])) != 0) ? 1 : 0;
        packed_border |= ((unsigned int)bd) << (8 * k);

        float s = 0.0f;
        #pragma unroll
        for (int c = 0; c < Cn; c++) s += __expf(v[c][k] - m);

        if (t[k] != 255) nll += (m + __logf(s)) - tv;
    }
    ((unsigned int*)g_pred)[idx4] = packed_pred;
    ((unsigned int*)g_tb)[idx4]   = packed_border;

    // block reduction -> atomicAdd
    #pragma unroll
    for (int o = 16; o > 0; o >>= 1)
        nll += __shfl_down_sync(0xFFFFFFFFu, nll, o);
    __shared__ float ws[8];
    int lane = threadIdx.x & 31, wid = threadIdx.x >> 5;
    if (lane == 0) ws[wid] = nll;
    __syncthreads();
    if (wid == 0) {
        float v2 = (lane < (blockDim.x >> 5)) ? ws[lane] : 0.0f;
        #pragma unroll
        for (int o = 4; o > 0; o >>= 1)
            v2 += __shfl_down_sync(0xFFFFFFFFu, v2, o);
        if (lane == 0) atomicAdd(&g_ce, v2);
    }
}

// ---------------------------------------------------------------------------
// Kernel 2: 2-D Chebyshev distance via expanding-ring search + pred-border
// masking + border-loss reduction. One 32x32 tile per block (32x8 threads,
// 4 rows/thread). Border halo 64x64 in shared (16-px apron); exact global
// fallback for d >= 16 (probability ~0 for this data, required for exactness).
// ---------------------------------------------------------------------------
__global__ void __launch_bounds__(256) dt_kernel() {
    __shared__ unsigned char sB[64 * 64];   // target-border halo
    __shared__ unsigned char sP[34 * 48];   // pred halo (33x33 needed)
    __shared__ int wsum[8];

    int bimg = blockIdx.z;
    int r0 = blockIdx.y * 32, c0 = blockIdx.x * 32;
    int tid = threadIdx.y * 32 + threadIdx.x;
    const unsigned char* tb = g_tb + bimg * HWn;
    const unsigned char* pp = g_pred + bimg * HWn;

    // Load border halo: 64 rows x 4 aligned 16B chunks; OOB chunk -> 0.
    {
        int row = tid >> 2, ch = tid & 3;
        int r = r0 - 16 + row;
        int c = c0 - 16 + ch * 16;           // multiple of 16
        uint4 val = make_uint4(0u, 0u, 0u, 0u);
        if (r >= 0 && r < Hn && c >= 0 && c < Wn)
            val = *(const uint4*)(tb + r * Wn + c);
        *(uint4*)(sB + row * 64 + ch * 16) = val;
    }
    // Load pred halo: 34 rows x 3 aligned 16B chunks; OOB chunk -> 0.
    if (tid < 102) {
        int row = tid / 3, ch = tid - row * 3;
        int r = r0 + row;
        int c = c0 + ch * 16;
        uint4 val = make_uint4(0u, 0u, 0u, 0u);
        if (r < Hn && c < Wn)
            val = *(const uint4*)(pp + r * Wn + c);
        *(uint4*)(sP + row * 48 + ch * 16) = val;
    }
    __syncthreads();

    int contrib = 0;
    #pragma unroll
    for (int k = 0; k < 4; k++) {
        int lr = threadIdx.y + k * 8;        // 0..31
        int lc = threadIdx.x;                // 0..31
        int gi = r0 + lr, gj = c0 + lc;

        // pred border at (gi, gj)
        int p0 = sP[lr * 48 + lc];
        int pr = (gj < Wn - 1) ? sP[lr * 48 + lc + 1]   : p0;
        int pd = (gi < Hn - 1) ? sP[(lr + 1) * 48 + lc] : p0;
        bool pb = (((pd - p0) + (pr - p0)) != 0);

        if (pb) {
            int sr = lr + 16, sc = lc + 16;
            int d;
            if (sB[sr * 64 + sc]) {
                d = 0;
            } else {
                int tt = 1;
                bool f = false;
                for (; tt < 16; tt++) {
                    f = false;
                    int top = (sr - tt) * 64, bot = (sr + tt) * 64;
                    for (int dx = -tt; dx <= tt; dx++)
                        f |= (sB[top + sc + dx] | sB[bot + sc + dx]) != 0;
                    for (int dy = -tt + 1; dy <= tt - 1; dy++) {
                        int rr = (sr + dy) * 64;
                        f |= (sB[rr + sc - tt] | sB[rr + sc + tt]) != 0;
                    }
                    if (f) break;
                }
                if (f) {
                    d = tt;
                } else {
                    // exact global fallback (essentially never taken)
                    d = BOUND;
                    for (; tt <= Hn + Wn; tt++) {
                        bool g = false;
                        int ra = gi - tt, rb = gi + tt;
                        int ca = gj - tt, cb = gj + tt;
                        int cl = ca > 0 ? ca : 0;
                        int cr = cb < Wn - 1 ? cb : Wn - 1;
                        if (ra >= 0) for (int c = cl; c <= cr; c++) g |= tb[ra * Wn + c] != 0;
                        if (rb < Hn) for (int c = cl; c <= cr; c++) g |= tb[rb * Wn + c] != 0;
                        int rl = (ra + 1) > 0 ? (ra + 1) : 0;
                        int rh = (rb - 1) < Hn - 1 ? (rb - 1) : Hn - 1;
                        if (ca >= 0) for (int r = rl; r <= rh; r++) g |= tb[r * Wn + ca] != 0;
                        if (cb < Wn) for (int r = rl; r <= rh; r++) g |= tb[r * Wn + cb] != 0;
                        if (g) { d = tt; break; }
                        if (ra < 0 && rb >= Hn && ca < 0 && cb >= Wn) break;  // whole image scanned
                    }
                }
            }
            contrib += d;
        }
    }

    // integer block reduction (exact) -> u32 atomic
    #pragma unroll
    for (int o = 16; o > 0; o >>= 1)
        contrib += __shfl_down_sync(0xFFFFFFFFu, contrib, o);
    int lane = tid & 31, wid = tid >> 5;
    if (lane == 0) wsum[wid] = contrib;
    __syncthreads();
    if (wid == 0) {
        int v2 = (lane < 8) ? wsum[lane] : 0;
        #pragma unroll
        for (int o = 4; o > 0; o >>= 1)
            v2 += __shfl_down_sync(0xFFFFFFFFu, v2, o);
        if (lane == 0) atomicAdd(&g_border, (unsigned int)v2);
    }
}

// ---------------------------------------------------------------------------
// Kernel 3: combine.
// ---------------------------------------------------------------------------
__global__ void final_kernel(float* out) {
    out[0] = g_ce + 0.2f * (float)g_border;
}

extern "C" void kernel_launch(void* const* d_in, const int* in_sizes, int n_in,
                              void* d_out, int out_size) {
    const float* slices  = (const float*)d_in[0];
    const int*   targets = (const int*)d_in[1];   // JAX int64 -> int32 (x64 disabled)
    float* out = (float*)d_out;

    init_kernel<<<1, 1>>>();
    ce_kernel<<<(NPIX / 4) / 256, 256>>>(slices, targets);
    dt_kernel<<<dim3(Wn / 32, Hn / 32, Bn), dim3(32, 8)>>>();
    final_kernel<<<1, 1>>>(out);
}